// round 11
// baseline (speedup 1.0000x reference)
#include <cuda_runtime.h>

// Problem constants (fixed by reference): B=2, S=2048, D=1024, H=16, HS=64
#define PB 2
#define PS 2048
#define PD 1024
#define PH 16
#define PHS 64
#define PBH (PB*PH)

// log2(e) / sqrt(HS) = 1.4426950408889634 / 8
#define QSCALE 0.18033688011112043f

// Attention smem: double-buffered K and V tiles, 64 rows x 68 floats each.
#define TILE_F (64 * 68)
#define ATTN_SMEM (4 * TILE_F * (int)sizeof(float))   // 2 bufs x (K + V) = 69632 B

// Scratch: Q,K,V in [B,H,S,HS] layout (16 MB each). __device__ globals are the
// sanctioned scratch mechanism (no allocations allowed).
__device__ float g_Q[PB*PH*PS*PHS];
__device__ float g_K[PB*PH*PS*PHS];
__device__ float g_V[PB*PH*PS*PHS];

// Fast exp2 via MUFU.EX2 (guaranteed, independent of fast-math flags).
// Inputs here are always <= 0 (softmax domain), well inside the safe range.
__device__ __forceinline__ float ex2(float x) {
    float r;
    asm("ex2.approx.ftz.f32 %0, %1;" : "=f"(r) : "f"(x));
    return r;
}

// ---------------------------------------------------------------------------
// QKV projection: C[m][n] = sum_k x[m][k] * W[n][k] + bias[n]
// M = B*S = 4096, N = D = 1024, K = D = 1024. blockIdx.z picks Q/K/V.
// 128x128 block tile, BK=8, 256 threads, 8x8 micro-tile per thread.
// Micro-tile is SPLIT 4+4 with stride 64 in both m and n: LDS.128 phase
// addresses are 128B contiguous -> conflict-free smem fragment loads.
// Double-buffered smem: ONE __syncthreads per k-tile. Register prefetch of
// the tile after next overlaps gmem latency with the FFMA block; all
// prefetch addressing is branch-free (clamped).
// Output scattered into [B,H,S,HS] layout for the attention kernel.
// ---------------------------------------------------------------------------
__global__ __launch_bounds__(256, 2)
void qkv_proj_kernel(const float* __restrict__ x,
                     const float* __restrict__ Wq, const float* __restrict__ bq,
                     const float* __restrict__ Wk, const float* __restrict__ bk,
                     const float* __restrict__ Wv, const float* __restrict__ bv)
{
    const int which = blockIdx.z;
    const float* __restrict__ W    = (which == 0) ? Wq : (which == 1) ? Wk : Wv;
    const float* __restrict__ bias = (which == 0) ? bq : (which == 1) ? bk : bv;
    float* __restrict__ out        = (which == 0) ? g_Q : (which == 1) ? g_K : g_V;

    __shared__ float As[2][8][132];   // [buf][k'][m'], padded stride 132
    __shared__ float Bs[2][8][132];   // [buf][k'][n']

    const int tid = threadIdx.x;
    const int tx  = tid & 15;      // 0..15 -> n direction
    const int ty  = tid >> 4;      // 0..15 -> m direction
    const int m0  = blockIdx.y * 128;
    const int n0  = blockIdx.x * 128;

    // Cooperative load mapping: each thread loads one float4 of A and one of W.
    const int lr = tid >> 1;          // 0..127 (row within tile)
    const int lc = (tid & 1) * 4;     // 0 or 4 (k offset)

    float acc[8][8];                  // [row group: 4 + 4@+64][col group: same]
    #pragma unroll
    for (int i = 0; i < 8; i++)
        #pragma unroll
        for (int j = 0; j < 8; j++)
            acc[i][j] = 0.0f;

    const float* aptr = x + (m0 + lr) * PD + lc;
    const float* bptr = W + (n0 + lr) * PD + lc;

    // Prologue: tile 0 -> smem buf 0; prefetch tile 1 into registers.
    {
        float4 a0 = *(const float4*)(aptr);
        float4 b0 = *(const float4*)(bptr);
        As[0][lc + 0][lr] = a0.x;  As[0][lc + 1][lr] = a0.y;
        As[0][lc + 2][lr] = a0.z;  As[0][lc + 3][lr] = a0.w;
        Bs[0][lc + 0][lr] = b0.x;  Bs[0][lc + 1][lr] = b0.y;
        Bs[0][lc + 2][lr] = b0.z;  Bs[0][lc + 3][lr] = b0.w;
    }
    __syncthreads();
    float4 a4 = *(const float4*)(aptr + 8);
    float4 b4 = *(const float4*)(bptr + 8);

    int buf = 0;
    #pragma unroll 2
    for (int k0 = 0; k0 < PD; k0 += 8) {
        // Stage the prefetched tile (k0+8) into the other buffer.
        // (Final iteration stores clamped re-read data to the dead buffer.)
        const int nb = buf ^ 1;
        As[nb][lc + 0][lr] = a4.x;  As[nb][lc + 1][lr] = a4.y;
        As[nb][lc + 2][lr] = a4.z;  As[nb][lc + 3][lr] = a4.w;
        Bs[nb][lc + 0][lr] = b4.x;  Bs[nb][lc + 1][lr] = b4.y;
        Bs[nb][lc + 2][lr] = b4.z;  Bs[nb][lc + 3][lr] = b4.w;

        // Branch-free prefetch of tile k0+16 (clamped, dead on last iters).
        {
            const int knext = (k0 + 16 < PD) ? (k0 + 16) : k0;  // SEL, no branch
            a4 = *(const float4*)(aptr + knext);
            b4 = *(const float4*)(bptr + knext);
        }

        // Compute on the current buffer. Split 4+4 fragments, conflict-free.
        #pragma unroll
        for (int kk = 0; kk < 8; kk++) {
            float a[8], b[8];
            *(float4*)(a)     = *(const float4*)&As[buf][kk][ty * 4];
            *(float4*)(a + 4) = *(const float4*)&As[buf][kk][ty * 4 + 64];
            *(float4*)(b)     = *(const float4*)&Bs[buf][kk][tx * 4];
            *(float4*)(b + 4) = *(const float4*)&Bs[buf][kk][tx * 4 + 64];
            #pragma unroll
            for (int i = 0; i < 8; i++)
                #pragma unroll
                for (int j = 0; j < 8; j++)
                    acc[i][j] += a[i] * b[j];
        }

        // Single barrier per tile: publishes buf^1 stores, retires buf reads.
        __syncthreads();
        buf = nb;
    }

    // Epilogue: bias add + scatter into [B,H,S,HS].
    // Thread owns rows {m0+ty*4+i, m0+ty*4+64+i} and cols
    // {n0+tx*4+j, n0+tx*4+64+j}, i,j in 0..3. Each 4-col group is 4-aligned
    // within a 64-wide head (4 | 64), so one float4 store per group.
    const int nc0 = n0 + tx * 4;
    const int nc1 = nc0 + 64;
    const int hh0 = nc0 >> 6, dd0 = nc0 & 63;
    const int hh1 = nc1 >> 6, dd1 = nc1 & 63;
    float4 bl0 = *(const float4*)(bias + nc0);
    float4 bl1 = *(const float4*)(bias + nc1);

    #pragma unroll
    for (int i = 0; i < 8; i++) {
        const int mrow = m0 + ty * 4 + ((i < 4) ? i : (64 + i - 4));
        const int bb = mrow >> 11;           // / 2048
        const int ss = mrow & 2047;
        float* base = out + (((size_t)(bb * PH) * PS) + ss) * PHS; // + hh*PS*PHS
        float4 r0, r1;
        r0.x = acc[i][0] + bl0.x; r0.y = acc[i][1] + bl0.y;
        r0.z = acc[i][2] + bl0.z; r0.w = acc[i][3] + bl0.w;
        r1.x = acc[i][4] + bl1.x; r1.y = acc[i][5] + bl1.y;
        r1.z = acc[i][6] + bl1.z; r1.w = acc[i][7] + bl1.w;
        *(float4*)(base + (size_t)hh0 * PS * PHS + dd0) = r0;
        *(float4*)(base + (size_t)hh1 * PS * PHS + dd1) = r1;
    }
}

// ---------------------------------------------------------------------------
// Attention tile body, specialized at compile time on DIAG (causal mask).
// The DIAG=false instantiation carries zero masking instructions.
// The exp2 pass is separated from the PV FFMA pass: MUFU latency is absorbed
// in its own loop and the PV loop stays pure FFMA for clean dual-issue.
// ---------------------------------------------------------------------------
template<bool DIAG>
__device__ __forceinline__ void process_tile(
    const float (&q)[64], float (&acc)[64], float& m, float& l,
    const float (*Ks)[68], const float (*Vs)[68],
    int qrow, int j0)
{
    #pragma unroll 1
    for (int c = 0; c < 2; c++) {            // 2 chunks of 32 keys
        float s[32];
        float cmax = -1e30f;
        #pragma unroll
        for (int jj = 0; jj < 32; jj++) {
            const int j = c * 32 + jj;
            // 4 independent partial sums -> 4-way ILP on the FFMA chain.
            float d0 = 0.0f, d1 = 0.0f, d2 = 0.0f, d3 = 0.0f;
            #pragma unroll
            for (int d4 = 0; d4 < 16; d4++) {
                float4 k4 = *(const float4*)&Ks[j][d4 * 4];
                d0 += q[4*d4+0] * k4.x;
                d1 += q[4*d4+1] * k4.y;
                d2 += q[4*d4+2] * k4.z;
                d3 += q[4*d4+3] * k4.w;
            }
            float dot = (d0 + d1) + (d2 + d3);
            if (DIAG) {
                if (j0 + j > qrow) dot = -1e30f;
            }
            s[jj] = dot;
            cmax = fmaxf(cmax, dot);
        }
        const float mnew  = fmaxf(m, cmax);
        const float alpha = ex2(m - mnew);
        m = mnew;
        l *= alpha;
        #pragma unroll
        for (int d = 0; d < 64; d++) acc[d] *= alpha;

        // Pass 1: all 32 exp2 (MUFU) + l partials; s[] becomes p[].
        float l0 = 0.0f, l1 = 0.0f, l2 = 0.0f, l3 = 0.0f;
        #pragma unroll
        for (int jj = 0; jj < 32; jj++) {
            const float p = ex2(s[jj] - m);
            s[jj] = p;
            if ((jj & 3) == 0) l0 += p;          // jj is compile-time constant
            else if ((jj & 3) == 1) l1 += p;     // after unroll: no runtime cost
            else if ((jj & 3) == 2) l2 += p;
            else l3 += p;
        }
        l += (l0 + l1) + (l2 + l3);

        // Pass 2: pure-FFMA PV accumulation.
        #pragma unroll
        for (int jj = 0; jj < 32; jj++) {
            const int j = c * 32 + jj;
            const float p = s[jj];
            #pragma unroll
            for (int d4 = 0; d4 < 16; d4++) {
                float4 v4 = *(const float4*)&Vs[j][d4 * 4];
                acc[4*d4+0] += p * v4.x;
                acc[4*d4+1] += p * v4.y;
                acc[4*d4+2] += p * v4.z;
                acc[4*d4+3] += p * v4.w;
            }
        }
    }
}

// ---------------------------------------------------------------------------
// Causal flash attention, fp32, exp2 domain.
// Grid: (S/128, H, B). Block: 128 threads, one q-row per thread (128 rows).
// K/V 64x64 tiles are DOUBLE-BUFFERED in dynamic smem and filled with
// cp.async (LDGSTS): the next tile's global loads overlap the current tile's
// compute, with ONE __syncthreads per tile and no register staging.
// Causality: thread t's diagonal tile is my_diag = q0 + (t & 64). Warps 0-1
// (rows t<64) skip the block's final tile; the skip condition is uniform per
// warp, and all threads still reach the barrier. Only the my_diag tile runs
// the masked template path.
// Blocks are launched longest-first (high q0 first) so the tail wave is
// filled by the short near-diagonal blocks.
// ---------------------------------------------------------------------------
__global__ __launch_bounds__(128)
void attn_kernel(float* __restrict__ out)
{
    extern __shared__ __align__(16) float smem[];
    float* Kbuf = smem;                 // [2][64][68]
    float* Vbuf = smem + 2 * TILE_F;    // [2][64][68]

    const int t  = threadIdx.x;            // 0..127 == local q row
    const int q0 = (gridDim.x - 1 - blockIdx.x) * 128;  // longest blocks first
    const int h  = blockIdx.y;
    const int b  = blockIdx.z;
    const int bh = b * PH + h;
    const int qrow    = q0 + t;
    const int my_diag = q0 + (t & 64);     // this thread's diagonal tile base
    const int last    = q0 + 64;           // final tile base for this block

    // Issue one 64x64 K+V tile load as a cp.async group (8+8 x 16B/thread).
    // Row stride 68 floats = 272 B (16B multiple): cp.async-legal and
    // bank-shift 4 per row -> conflict-free smem writes.
    auto issue_tile = [&](int j0, int bufi) {
        const float4* Kg = (const float4*)(g_K + ((size_t)bh * PS + j0) * PHS);
        const float4* Vg = (const float4*)(g_V + ((size_t)bh * PS + j0) * PHS);
        float* Kd = Kbuf + bufi * TILE_F;
        float* Vd = Vbuf + bufi * TILE_F;
        #pragma unroll
        for (int i = 0; i < 8; i++) {
            const int v4  = t + 128 * i;          // float4 index in 64x64 tile
            const int row = v4 >> 4;
            const int c4  = (v4 & 15) * 4;
            unsigned ks = (unsigned)__cvta_generic_to_shared(Kd + row * 68 + c4);
            unsigned vs = (unsigned)__cvta_generic_to_shared(Vd + row * 68 + c4);
            asm volatile("cp.async.cg.shared.global [%0], [%1], 16;"
                         :: "r"(ks), "l"(Kg + v4) : "memory");
            asm volatile("cp.async.cg.shared.global [%0], [%1], 16;"
                         :: "r"(vs), "l"(Vg + v4) : "memory");
        }
        asm volatile("cp.async.commit_group;" ::: "memory");
    };

    // Prologue: start tile 0 immediately; Q row loads overlap it.
    issue_tile(0, 0);

    // Q row into registers, pre-scaled by log2(e)/sqrt(HS).
    float q[64];
    {
        const float4* Qg = (const float4*)(g_Q + ((size_t)bh * PS + qrow) * PHS);
        #pragma unroll
        for (int d4 = 0; d4 < 16; d4++) {
            float4 v = Qg[d4];
            q[4*d4+0] = v.x * QSCALE;
            q[4*d4+1] = v.y * QSCALE;
            q[4*d4+2] = v.z * QSCALE;
            q[4*d4+3] = v.w * QSCALE;
        }
    }

    float acc[64];
    #pragma unroll
    for (int d = 0; d < 64; d++) acc[d] = 0.0f;
    float m = -1e30f, l = 0.0f;

    int cur = 0;
    for (int j0 = 0; j0 <= last; j0 += 64) {
        // Wait own copies for buf[cur]; barrier publishes them block-wide AND
        // confirms buf[cur^1] fully consumed (safe to overwrite below).
        asm volatile("cp.async.wait_group 0;" ::: "memory");
        __syncthreads();
        if (j0 < last) issue_tile(j0 + 64, cur ^ 1);

        const float (*Ks)[68] = (const float (*)[68])(Kbuf + cur * TILE_F);
        const float (*Vs)[68] = (const float (*)[68])(Vbuf + cur * TILE_F);

        if (j0 < my_diag)
            process_tile<false>(q, acc, m, l, Ks, Vs, qrow, j0);
        else if (j0 == my_diag)
            process_tile<true >(q, acc, m, l, Ks, Vs, qrow, j0);
        // j0 > my_diag: warps 0-1 idle on the block's final tile (warp-uniform)

        cur ^= 1;
    }

    const float inv = 1.0f / l;
    float4* og = (float4*)(out + ((size_t)(b * PS + qrow)) * PD + h * PHS);
    #pragma unroll
    for (int d4 = 0; d4 < 16; d4++) {
        float4 r;
        r.x = acc[4*d4+0] * inv;
        r.y = acc[4*d4+1] * inv;
        r.z = acc[4*d4+2] * inv;
        r.w = acc[4*d4+3] * inv;
        og[d4] = r;
    }
}

// ---------------------------------------------------------------------------
extern "C" void kernel_launch(void* const* d_in, const int* in_sizes, int n_in,
                              void* d_out, int out_size)
{
    const float* x  = (const float*)d_in[0];
    const float* Wq = (const float*)d_in[1];
    const float* bq = (const float*)d_in[2];
    const float* Wk = (const float*)d_in[3];
    const float* bk = (const float*)d_in[4];
    const float* Wv = (const float*)d_in[5];
    const float* bv = (const float*)d_in[6];
    float* out = (float*)d_out;

    // QKV projections: grid (N/128, M/128, 3)
    dim3 g1(PD / 128, (PB * PS) / 128, 3);
    qkv_proj_kernel<<<g1, 256>>>(x, Wq, bq, Wk, bk, Wv, bv);

    // Attention: grid (S/128, H, B). Dynamic smem > 48KB needs the opt-in
    // attribute (idempotent host call; not an allocation, capture-safe).
    cudaFuncSetAttribute(attn_kernel,
                         cudaFuncAttributeMaxDynamicSharedMemorySize, ATTN_SMEM);
    dim3 g2(PS / 128, PH, PB);
    attn_kernel<<<g2, 128, ATTN_SMEM>>>(out);
}

// round 14
// speedup vs baseline: 1.7935x; 1.7935x over previous
#include <cuda_runtime.h>

// Problem constants (fixed by reference): B=2, S=2048, D=1024, H=16, HS=64
#define PB 2
#define PS 2048
#define PD 1024
#define PH 16
#define PHS 64

// log2(e) / sqrt(HS) = 1.4426950408889634 / 8  (folded into Q at projection)
#define QSCALE 0.18033688011112043f

// Attention smem: Qt[64][132] + double-buffered Kt[64][68] and Vs[64][68].
#define QT_F   (64 * 132)
#define TILE_F (64 * 68)
#define ATTN_SMEM ((QT_F + 4 * TILE_F) * (int)sizeof(float))   // 103424 B

// Scratch (allocation-free): Q,K stored TRANSPOSED per head [bh][64 d][2048 s];
// V stored [bh][2048 s][64 d].
__device__ float g_Q[PB*PH*PS*PHS];
__device__ float g_K[PB*PH*PS*PHS];
__device__ float g_V[PB*PH*PS*PHS];

__device__ __forceinline__ float ex2(float x) {
    float r;
    asm("ex2.approx.ftz.f32 %0, %1;" : "=f"(r) : "f"(x));
    return r;
}

// ---------------------------------------------------------------------------
// QKV projection GEMM: 128x128x8 tiles, 256 threads, split 4+4 micro-tile,
// double-buffered smem (one barrier per k-tile), register prefetch.
// Epilogue: Q/K written TRANSPOSED [bh][d][s] (coalesced along s), Q
// pre-scaled by QSCALE; V written [bh][s][d].
// ---------------------------------------------------------------------------
__global__ __launch_bounds__(256, 2)
void qkv_proj_kernel(const float* __restrict__ x,
                     const float* __restrict__ Wq, const float* __restrict__ bq,
                     const float* __restrict__ Wk, const float* __restrict__ bk,
                     const float* __restrict__ Wv, const float* __restrict__ bv)
{
    const int which = blockIdx.z;
    const float* __restrict__ W    = (which == 0) ? Wq : (which == 1) ? Wk : Wv;
    const float* __restrict__ bias = (which == 0) ? bq : (which == 1) ? bk : bv;
    float* __restrict__ out        = (which == 0) ? g_Q : (which == 1) ? g_K : g_V;

    __shared__ float As[2][8][132];
    __shared__ float Bs[2][8][132];

    const int tid = threadIdx.x;
    const int tx  = tid & 15;
    const int ty  = tid >> 4;
    const int m0  = blockIdx.y * 128;
    const int n0  = blockIdx.x * 128;

    const int lr = tid >> 1;
    const int lc = (tid & 1) * 4;

    float acc[8][8];
    #pragma unroll
    for (int i = 0; i < 8; i++)
        #pragma unroll
        for (int j = 0; j < 8; j++)
            acc[i][j] = 0.0f;

    const float* aptr = x + (m0 + lr) * PD + lc;
    const float* bptr = W + (n0 + lr) * PD + lc;

    {
        float4 a0 = *(const float4*)(aptr);
        float4 b0 = *(const float4*)(bptr);
        As[0][lc + 0][lr] = a0.x;  As[0][lc + 1][lr] = a0.y;
        As[0][lc + 2][lr] = a0.z;  As[0][lc + 3][lr] = a0.w;
        Bs[0][lc + 0][lr] = b0.x;  Bs[0][lc + 1][lr] = b0.y;
        Bs[0][lc + 2][lr] = b0.z;  Bs[0][lc + 3][lr] = b0.w;
    }
    __syncthreads();
    float4 a4 = *(const float4*)(aptr + 8);
    float4 b4 = *(const float4*)(bptr + 8);

    int buf = 0;
    #pragma unroll 2
    for (int k0 = 0; k0 < PD; k0 += 8) {
        const int nb = buf ^ 1;
        As[nb][lc + 0][lr] = a4.x;  As[nb][lc + 1][lr] = a4.y;
        As[nb][lc + 2][lr] = a4.z;  As[nb][lc + 3][lr] = a4.w;
        Bs[nb][lc + 0][lr] = b4.x;  Bs[nb][lc + 1][lr] = b4.y;
        Bs[nb][lc + 2][lr] = b4.z;  Bs[nb][lc + 3][lr] = b4.w;

        {
            const int knext = (k0 + 16 < PD) ? (k0 + 16) : k0;
            a4 = *(const float4*)(aptr + knext);
            b4 = *(const float4*)(bptr + knext);
        }

        #pragma unroll
        for (int kk = 0; kk < 8; kk++) {
            float a[8], b[8];
            *(float4*)(a)     = *(const float4*)&As[buf][kk][ty * 4];
            *(float4*)(a + 4) = *(const float4*)&As[buf][kk][ty * 4 + 64];
            *(float4*)(b)     = *(const float4*)&Bs[buf][kk][tx * 4];
            *(float4*)(b + 4) = *(const float4*)&Bs[buf][kk][tx * 4 + 64];
            #pragma unroll
            for (int i = 0; i < 8; i++)
                #pragma unroll
                for (int j = 0; j < 8; j++)
                    acc[i][j] += a[i] * b[j];
        }

        __syncthreads();
        buf = nb;
    }

    const int nc0 = n0 + tx * 4;
    const int nc1 = nc0 + 64;
    float blv[8];
    *(float4*)(blv)     = *(const float4*)(bias + nc0);
    *(float4*)(blv + 4) = *(const float4*)(bias + nc1);
    const int bb  = m0 >> 11;           // block fully inside one batch
    const int ss0 = (m0 & 2047) + ty * 4;

    if (which == 2) {
        // V epilogue: [bh][s][d]
        const int hh0 = nc0 >> 6, dd0 = nc0 & 63;
        const int hh1 = nc1 >> 6, dd1 = nc1 & 63;
        #pragma unroll
        for (int i = 0; i < 8; i++) {
            const int mrow = m0 + ty * 4 + ((i < 4) ? i : (60 + i));
            const int ss = mrow & 2047;
            float* base = out + (((size_t)(bb * PH) * PS) + ss) * PHS;
            float4 r0, r1;
            r0.x = acc[i][0] + blv[0]; r0.y = acc[i][1] + blv[1];
            r0.z = acc[i][2] + blv[2]; r0.w = acc[i][3] + blv[3];
            r1.x = acc[i][4] + blv[4]; r1.y = acc[i][5] + blv[5];
            r1.z = acc[i][6] + blv[6]; r1.w = acc[i][7] + blv[7];
            *(float4*)(base + (size_t)hh0 * PS * PHS + dd0) = r0;
            *(float4*)(base + (size_t)hh1 * PS * PHS + dd1) = r1;
        }
    } else {
        // Q/K epilogue: transposed [bh][d][s]; Q pre-scaled by QSCALE.
        const float sc = (which == 0) ? QSCALE : 1.0f;
        #pragma unroll
        for (int j = 0; j < 8; j++) {
            const int col = n0 + tx * 4 + ((j < 4) ? j : (60 + j));
            const int hh = col >> 6, dl = col & 63;
            const float bj = blv[j];
            float4 r0, r1;
            r0.x = (acc[0][j] + bj) * sc; r0.y = (acc[1][j] + bj) * sc;
            r0.z = (acc[2][j] + bj) * sc; r0.w = (acc[3][j] + bj) * sc;
            r1.x = (acc[4][j] + bj) * sc; r1.y = (acc[5][j] + bj) * sc;
            r1.z = (acc[6][j] + bj) * sc; r1.w = (acc[7][j] + bj) * sc;
            float* dst = out + (((size_t)(bb * PH + hh) * 64) + dl) * PS + ss0;
            *(float4*)(dst)      = r0;     // rows ss0..ss0+3
            *(float4*)(dst + 64) = r1;     // rows ss0+64..ss0+67
        }
    }
}

// ---------------------------------------------------------------------------
// Causal flash attention as two register-tiled GEMMs.
// Block: 128 threads (ty=tid/8 rows, tx=tid%8 keys/cols), 128 q-rows/block,
// 64-key tiles. Each thread: 8x8 score tile + 8x8 output tile (64 independent
// FFMA chains; 16:1 FFMA:LDS). Softmax row-reductions via 8-lane shfl.bfly;
// PV P-operand via shfl.idx from same-row lanes. cp.async double buffering.
// ---------------------------------------------------------------------------
__global__ __launch_bounds__(128)
void attn_kernel(float* __restrict__ out)
{
    extern __shared__ __align__(16) float smem[];
    float* Qt  = smem;                   // [64][132]
    float* KtB = smem + QT_F;            // [2][64][68]
    float* VsB = KtB + 2 * TILE_F;       // [2][64][68]

    const int tid = threadIdx.x;
    const int tx  = tid & 7;             // key/col group
    const int ty  = tid >> 3;            // row group (0..15)
    const int tx4 = tx * 4, ty4 = ty * 4;
    const int q0  = (gridDim.x - 1 - blockIdx.x) * 128;   // longest-first
    const int h   = blockIdx.y;
    const int b   = blockIdx.z;
    const int bh  = b * PH + h;

    const float* Qg = g_Q + (size_t)bh * 64 * PS;   // [64][2048]
    const float* Kg = g_K + (size_t)bh * 64 * PS;   // [64][2048]
    const float* Vg = g_V + (size_t)bh * PS * 64;   // [2048][64]

    auto issue_tile = [&](int j0, int bufi) {
        float* Kd = KtB + bufi * TILE_F;
        float* Vd = VsB + bufi * TILE_F;
        #pragma unroll
        for (int it = 0; it < 8; it++) {
            const int c = tid + 128 * it;          // 0..1023
            const int r = c >> 4, off = (c & 15) * 4;
            unsigned kd = (unsigned)__cvta_generic_to_shared(Kd + r * 68 + off);
            unsigned vd = (unsigned)__cvta_generic_to_shared(Vd + r * 68 + off);
            asm volatile("cp.async.cg.shared.global [%0], [%1], 16;"
                         :: "r"(kd), "l"(Kg + r * PS + j0 + off) : "memory");
            asm volatile("cp.async.cg.shared.global [%0], [%1], 16;"
                         :: "r"(vd), "l"(Vg + (size_t)(j0 + r) * 64 + off) : "memory");
        }
        asm volatile("cp.async.commit_group;" ::: "memory");
    };

    // Prologue: Qt (block's Q slice, [d][s] layout) + tile 0, one group.
    #pragma unroll
    for (int it = 0; it < 16; it++) {
        const int c = tid + 128 * it;              // 0..2047
        const int d = c >> 5, off = (c & 31) * 4;
        unsigned qd = (unsigned)__cvta_generic_to_shared(Qt + d * 132 + off);
        asm volatile("cp.async.cg.shared.global [%0], [%1], 16;"
                     :: "r"(qd), "l"(Qg + d * PS + q0 + off) : "memory");
    }
    issue_tile(0, 0);

    float acc[8][8];
    #pragma unroll
    for (int i = 0; i < 8; i++)
        #pragma unroll
        for (int j = 0; j < 8; j++) acc[i][j] = 0.0f;
    float m[8], l[8];
    #pragma unroll
    for (int i = 0; i < 8; i++) { m[i] = -1e30f; l[i] = 0.0f; }

    const int last = q0 + 64;
    const int laneBase = (ty & 3) * 8;
    int cur = 0;

    for (int j0 = 0; j0 <= last; j0 += 64) {
        asm volatile("cp.async.wait_group 0;" ::: "memory");
        __syncthreads();
        if (j0 < last) issue_tile(j0 + 64, cur ^ 1);

        const float* KtC = KtB + cur * TILE_F;
        const float* VsC = VsB + cur * TILE_F;

        // ---- Score GEMM: s[8][8] += Qt[d][rows] * Kt[d][keys] over d ----
        float s[8][8];
        #pragma unroll
        for (int i = 0; i < 8; i++)
            #pragma unroll
            for (int j = 0; j < 8; j++) s[i][j] = 0.0f;

        #pragma unroll 8
        for (int d = 0; d < 64; d++) {
            float a[8], bb2[8];
            *(float4*)(a)       = *(const float4*)(Qt + d * 132 + ty4);
            *(float4*)(a + 4)   = *(const float4*)(Qt + d * 132 + ty4 + 64);
            *(float4*)(bb2)     = *(const float4*)(KtC + d * 68 + tx4);
            *(float4*)(bb2 + 4) = *(const float4*)(KtC + d * 68 + tx4 + 32);
            #pragma unroll
            for (int i = 0; i < 8; i++)
                #pragma unroll
                for (int j = 0; j < 8; j++)
                    s[i][j] += a[i] * bb2[j];
        }

        // ---- Causal mask (only the last two tiles can clip) ----
        if (j0 >= q0) {
            #pragma unroll
            for (int i = 0; i < 8; i++) {
                const int row = q0 + ty4 + ((i < 4) ? i : (60 + i));
                #pragma unroll
                for (int j = 0; j < 8; j++) {
                    const int key = j0 + tx4 + ((j < 4) ? j : (28 + j));
                    if (key > row) s[i][j] = -1e30f;
                }
            }
        }

        // ---- Online softmax per row (8-lane bfly reductions) ----
        #pragma unroll
        for (int i = 0; i < 8; i++) {
            float t0 = fmaxf(fmaxf(s[i][0], s[i][1]), fmaxf(s[i][2], s[i][3]));
            float t1 = fmaxf(fmaxf(s[i][4], s[i][5]), fmaxf(s[i][6], s[i][7]));
            float tm = fmaxf(t0, t1);
            tm = fmaxf(tm, __shfl_xor_sync(0xffffffffu, tm, 1));
            tm = fmaxf(tm, __shfl_xor_sync(0xffffffffu, tm, 2));
            tm = fmaxf(tm, __shfl_xor_sync(0xffffffffu, tm, 4));
            const float mn    = fmaxf(m[i], tm);
            const float alpha = ex2(m[i] - mn);
            m[i] = mn;
            float ps = 0.0f;
            #pragma unroll
            for (int j = 0; j < 8; j++) {
                const float p = ex2(s[i][j] - mn);
                s[i][j] = p;
                ps += p;
            }
            ps += __shfl_xor_sync(0xffffffffu, ps, 1);
            ps += __shfl_xor_sync(0xffffffffu, ps, 2);
            ps += __shfl_xor_sync(0xffffffffu, ps, 4);
            l[i] = l[i] * alpha + ps;
            #pragma unroll
            for (int j = 0; j < 8; j++) acc[i][j] *= alpha;
        }

        // ---- PV GEMM: acc[8][8] += P[rows][k] * Vs[k][cols] ----
        #pragma unroll
        for (int g = 0; g < 2; g++) {
            #pragma unroll 2
            for (int stx = 0; stx < 8; stx++) {
                const int srcLane = laneBase + stx;
                const float* vrow = VsC + (g * 32 + stx * 4) * 68 + tx4;
                #pragma unroll
                for (int jp = 0; jp < 4; jp++) {
                    float a[8];
                    #pragma unroll
                    for (int i = 0; i < 8; i++)
                        a[i] = __shfl_sync(0xffffffffu, s[i][g * 4 + jp], srcLane);
                    float4 v0 = *(const float4*)(vrow + jp * 68);
                    float4 v1 = *(const float4*)(vrow + jp * 68 + 32);
                    #pragma unroll
                    for (int i = 0; i < 8; i++) {
                        acc[i][0] += a[i] * v0.x; acc[i][1] += a[i] * v0.y;
                        acc[i][2] += a[i] * v0.z; acc[i][3] += a[i] * v0.w;
                        acc[i][4] += a[i] * v1.x; acc[i][5] += a[i] * v1.y;
                        acc[i][6] += a[i] * v1.z; acc[i][7] += a[i] * v1.w;
                    }
                }
            }
        }

        cur ^= 1;
    }

    // ---- Epilogue: normalize and store [b][s][h*64+col] ----
    #pragma unroll
    for (int i = 0; i < 8; i++) {
        const int row = q0 + ty4 + ((i < 4) ? i : (60 + i));
        const float inv = 1.0f / l[i];
        float* dst = out + ((size_t)(b * PS + row)) * PD + h * PHS;
        float4 o0, o1;
        o0.x = acc[i][0] * inv; o0.y = acc[i][1] * inv;
        o0.z = acc[i][2] * inv; o0.w = acc[i][3] * inv;
        o1.x = acc[i][4] * inv; o1.y = acc[i][5] * inv;
        o1.z = acc[i][6] * inv; o1.w = acc[i][7] * inv;
        *(float4*)(dst + tx4)      = o0;
        *(float4*)(dst + tx4 + 32) = o1;
    }
}

// ---------------------------------------------------------------------------
extern "C" void kernel_launch(void* const* d_in, const int* in_sizes, int n_in,
                              void* d_out, int out_size)
{
    const float* x  = (const float*)d_in[0];
    const float* Wq = (const float*)d_in[1];
    const float* bq = (const float*)d_in[2];
    const float* Wk = (const float*)d_in[3];
    const float* bk = (const float*)d_in[4];
    const float* Wv = (const float*)d_in[5];
    const float* bv = (const float*)d_in[6];
    float* out = (float*)d_out;

    dim3 g1(PD / 128, (PB * PS) / 128, 3);
    qkv_proj_kernel<<<g1, 256>>>(x, Wq, bq, Wk, bk, Wv, bv);

    cudaFuncSetAttribute(attn_kernel,
                         cudaFuncAttributeMaxDynamicSharedMemorySize, ATTN_SMEM);
    dim3 g2(PS / 128, PH, PB);
    attn_kernel<<<g2, 128, ATTN_SMEM>>>(out);
}